// round 15
// baseline (speedup 1.0000x reference)
#include <cuda_runtime.h>

// ---------------- problem-size capacities (fixed by dataset) ----------------
static const int NMAX  = 100000;
static const int EMAX  = 500000;
static const int QMAXC = 128;

// ---------------- device scratch (static; no allocation) --------------------
__device__ float    dM[128 * 128];          // M = Wq^T @ Wk
__device__ float    dGx[QMAXC * 32];
__device__ float    dGy[QMAXC * 32];
__device__ float    dGrel[QMAXC * 32];
__device__ float    dCq[QMAXC];
__device__ float    dZ[NMAX * 32];
__device__ float    dP[NMAX * 32];
__device__ float    dT[NMAX * 32];
__device__ float    dRepr[NMAX * 32];
__device__ float    dAgg[NMAX * 32];
__device__ float    dLogits1[EMAX];         // layer-1: quad term, then logit
__device__ float    dLogits0[EMAX];         // layer-0: quad term, then logit
__device__ float    dEx[EMAX];              // exp, then normalized w
__device__ unsigned dTsEnc[EMAX];
__device__ unsigned dNodeMax[NMAX];
__device__ float    dNodeSum[NMAX];
__device__ int      dOff[QMAXC + 1];
__device__ int      dKlist[EMAX];
__device__ int      dKcount;

// ---------------- helpers ----------------------------------------------------
__device__ __forceinline__ unsigned encf(float f) {
    unsigned u = __float_as_uint(f);
    return (u & 0x80000000u) ? ~u : (u | 0x80000000u);
}
__device__ __forceinline__ float decf(unsigned e) {
    unsigned u = (e & 0x80000000u) ? (e & 0x7FFFFFFFu) : ~e;
    return __uint_as_float(u);
}
__device__ __forceinline__ unsigned long long packf2(float lo, float hi) {
    unsigned long long r;
    asm("mov.b64 %0, {%1, %2};" : "=l"(r) : "f"(lo), "f"(hi));
    return r;
}
__device__ __forceinline__ void unpackf2(unsigned long long v, float& lo, float& hi) {
    asm("mov.b64 {%0, %1}, %2;" : "=f"(lo), "=f"(hi) : "l"(v));
}
__device__ __forceinline__ unsigned long long fmaf2(unsigned long long a, unsigned long long b,
                                                    unsigned long long c) {
    unsigned long long d;
    asm("fma.rn.f32x2 %0, %1, %2, %3;" : "=l"(d) : "l"(a), "l"(b), "l"(c));
    return d;
}
__device__ __forceinline__ void red4(float* p, float a, float b, float c, float d) {
    asm volatile("red.global.v4.f32.add [%0], {%1, %2, %3, %4};"
                 :: "l"(p), "f"(a), "f"(b), "f"(c), "f"(d) : "memory");
}
// streaming (evict-first) vector load: for single-use data
__device__ __forceinline__ float4 ldcs4(const float* p) {
    float4 v;
    asm volatile("ld.global.cs.v4.f32 {%0, %1, %2, %3}, [%4];"
                 : "=f"(v.x), "=f"(v.y), "=f"(v.z), "=f"(v.w) : "l"(p));
    return v;
}

// ---------------- prep: computeM + query_pre + group_off + resets -------------
__global__ void __launch_bounds__(128) prep_k(const float* __restrict__ Wq,
                                              const float* __restrict__ Wk,
                                              const float* __restrict__ qemb,
                                              const float* __restrict__ remb,
                                              const int* __restrict__ eg1,
                                              float* __restrict__ score_out,
                                              int N, int E1, int Q) {
    int b = blockIdx.x, t = threadIdx.x;
    if (b < 128) {
        int i = b, j = t;
        float acc = 0.f;
        #pragma unroll 8
        for (int o = 0; o < 128; o++)
            acc = fmaf(__ldg(&Wq[o * 128 + i]), __ldg(&Wk[o * 128 + j]), acc);
        dM[i * 128 + j] = acc;
        return;
    }
    if (b < 128 + Q) {
        if (t >= 32) return;
        int q = b - 128, d = t;
        __shared__ float qv[32], rv[32];
        qv[d] = qemb[q * 32 + d];
        rv[d] = remb[q * 32 + d];
        __syncwarp();
        __shared__ float su[128], sv[128];
        for (int o = d; o < 128; o += 32) {
            float uu = 0.f, vv = 0.f;
            #pragma unroll
            for (int c = 0; c < 32; c++) {
                uu = fmaf(__ldg(&Wk[o * 128 + 64 + c]), qv[c], uu);
                uu = fmaf(__ldg(&Wk[o * 128 + 96 + c]), rv[c], uu);
                vv = fmaf(__ldg(&Wq[o * 128 + 64 + c]), qv[c], vv);
                vv = fmaf(__ldg(&Wq[o * 128 + 96 + c]), rv[c], vv);
            }
            su[o] = uu; sv[o] = vv;
        }
        __syncwarp();
        float gx = 0.f, gy = 0.f, gr = 0.f, cq = 0.f;
        for (int o = 0; o < 128; o++) {
            float uo = su[o], vo = sv[o];
            gx = fmaf(__ldg(&Wq[o * 128 + d]), uo, gx);
            gy = fmaf(__ldg(&Wk[o * 128 + d]), vo, gy);
            gr = fmaf(__ldg(&Wq[o * 128 + 32 + d]), uo, gr);
            gr = fmaf(__ldg(&Wk[o * 128 + 32 + d]), vo, gr);
            if (d == 0) cq = fmaf(uo, vo, cq);
        }
        dGx[q * 32 + d] = gx;
        dGy[q * 32 + d] = gy;
        dGrel[q * 32 + d] = gr;
        if (d == 0) dCq[q] = cq;
        return;
    }
    if (b == 128 + Q) {
        for (int g = t; g <= Q; g += 128) {
            int lo = 0, hi = E1;
            while (lo < hi) {
                int mid = (lo + hi) >> 1;
                if (eg1[mid] < g) lo = mid + 1; else hi = mid;
            }
            dOff[g] = lo;
        }
        return;
    }
    int i = (b - (129 + Q)) * 128 + t;
    if (i < N * 32) dAgg[i] = 0.f;
    if (i < N) {
        dNodeMax[i] = 0u;
        dNodeSum[i] = 0.f;
        score_out[i] = 0.f;
    }
    if (i == 0) dKcount = 0;
}

// ---------------- device bodies: node precompute / quad -----------------------
// node body: 128 threads, 128 nodes. sW: 96*32 floats, sR: 128*33 floats.
__device__ __forceinline__ void node_pre_body(const float* __restrict__ repr_ext,
                                              int mode, int N, int base, int t,
                                              float* sW, float* sR) {
    for (int i = t; i < 96 * 32; i += 128) {
        int o = i >> 5, k = i & 31;
        float v;
        if (o < 32)      v = dM[o * 128 + k];
        else if (o < 64) v = dM[k * 128 + 32 + (o - 32)];
        else             v = dM[(32 + (o - 64)) * 128 + k];
        sW[i] = v;
    }
    if (mode == 0) {
        for (int i = t; i < 128 * 32; i += 128) {
            int n = base + (i >> 5);
            sR[(i >> 5) * 33 + (i & 31)] = (n < N) ? repr_ext[n * 32 + (i & 31)] : 0.f;
        }
    } else {
        for (int i = t; i < 128 * 32; i += 128) {
            int n = base + (i >> 5);
            float v = 0.f;
            if (n < N) {
                int g = n * 32 + (i & 31);
                v = fmaf(0.8f, dAgg[g], 0.2f * repr_ext[g]);
                dRepr[g] = v;
                dAgg[g] = 0.f;
            }
            sR[(i >> 5) * 33 + (i & 31)] = v;
        }
        int n = base + t;
        if (n < N) { dNodeMax[n] = 0u; dNodeSum[n] = 0.f; }
    }
    __syncthreads();
    float re[32];
    #pragma unroll
    for (int k = 0; k < 32; k++) re[k] = sR[t * 33 + k];

    const float4* Wv = reinterpret_cast<const float4*>(sW);
    bool live = (base + t) < N;
    #pragma unroll 1
    for (int c = 0; c < 3; c++) {
        float* out = (c == 0) ? dZ : (c == 1) ? dP : dT;
        #pragma unroll 1
        for (int h = 0; h < 2; h++) {
            float acc[16];
            #pragma unroll
            for (int o = 0; o < 16; o++) {
                int row = c * 32 + h * 16 + o;
                float a = 0.f;
                #pragma unroll
                for (int k4 = 0; k4 < 8; k4++) {
                    float4 m = Wv[row * 8 + k4];
                    a = fmaf(m.x, re[4 * k4 + 0], a);
                    a = fmaf(m.y, re[4 * k4 + 1], a);
                    a = fmaf(m.z, re[4 * k4 + 2], a);
                    a = fmaf(m.w, re[4 * k4 + 3], a);
                }
                acc[o] = a;
            }
            __syncthreads();
            if (live) {
                #pragma unroll
                for (int o = 0; o < 16; o++) sR[t * 17 + o] = acc[o];
            }
            __syncthreads();
            for (int i = t; i < 128 * 16; i += 128) {
                int n = base + (i >> 4);
                if (n < N) out[n * 32 + h * 16 + (i & 15)] = sR[(i >> 4) * 17 + (i & 15)];
            }
        }
    }
}

// quad body: 128 threads, 256 edges (2/thread via f32x2). sTri: 528 u64,
// sRe: 128*33 floats. rel read with streaming hint (single-use).
__device__ __forceinline__ void quad_body(const float* __restrict__ rel,
                                          float* __restrict__ out, int E,
                                          int base, int t,
                                          unsigned long long* sTri, float* sRe) {
    for (int i = t; i < 528; i += 128) {
        int j = 0, off = 0;
        while (off + (32 - j) <= i) { off += 32 - j; j++; }
        int k = j + (i - off);
        float v = (k == j) ? dM[(32 + j) * 128 + 32 + j]
                           : dM[(32 + j) * 128 + 32 + k] + dM[(32 + k) * 128 + 32 + j];
        sTri[i] = packf2(v, v);
    }
    // stage A: 128 edges (streaming loads)
    for (int i = t; i < 128 * 8; i += 128) {
        int erow = i >> 3, c4 = i & 7;
        int e = base + erow;
        float4 v = (e < E) ? ldcs4(&rel[(size_t)e * 32 + c4 * 4])
                           : make_float4(0.f, 0.f, 0.f, 0.f);
        sRe[erow * 33 + c4 * 4 + 0] = v.x;
        sRe[erow * 33 + c4 * 4 + 1] = v.y;
        sRe[erow * 33 + c4 * 4 + 2] = v.z;
        sRe[erow * 33 + c4 * 4 + 3] = v.w;
    }
    __syncthreads();
    float reA[32];
    #pragma unroll
    for (int k = 0; k < 32; k++) reA[k] = sRe[t * 33 + k];
    __syncthreads();
    for (int i = t; i < 128 * 8; i += 128) {
        int erow = i >> 3, c4 = i & 7;
        int e = base + 128 + erow;
        float4 v = (e < E) ? ldcs4(&rel[(size_t)e * 32 + c4 * 4])
                           : make_float4(0.f, 0.f, 0.f, 0.f);
        sRe[erow * 33 + c4 * 4 + 0] = v.x;
        sRe[erow * 33 + c4 * 4 + 1] = v.y;
        sRe[erow * 33 + c4 * 4 + 2] = v.z;
        sRe[erow * 33 + c4 * 4 + 3] = v.w;
    }
    __syncthreads();
    unsigned long long re2[32];
    #pragma unroll
    for (int k = 0; k < 32; k++) re2[k] = packf2(reA[k], sRe[t * 33 + k]);

    const unsigned long long z2 = packf2(0.f, 0.f);
    unsigned long long w2 = z2;
    #pragma unroll
    for (int j = 0; j < 32; j++) {
        const int off = 32 * j - (j * (j - 1)) / 2;
        unsigned long long v2 = fmaf2(sTri[off], re2[j], z2);
        #pragma unroll
        for (int k = j + 1; k < 32; k++)
            v2 = fmaf2(sTri[off + (k - j)], re2[k], v2);
        w2 = fmaf2(re2[j], v2, w2);
    }
    float wA, wB;
    unpackf2(w2, wA, wB);
    int eA = base + t, eB = base + 128 + t;
    if (eA < E) out[eA] = wA;
    if (eB < E) out[eB] = wB;
}

// ---------------- phase A: node_pre(mode 0) + quad(layer1) + quad(layer0) -----
static const int PHASEA_SMEM = 96 * 32 * 4 + 128 * 33 * 4;   // 29184 bytes
__global__ void __launch_bounds__(128) phaseA_k(const float* __restrict__ repr_ext,
                                                const float* __restrict__ rel1,
                                                const float* __restrict__ rel0,
                                                int N, int E1, int E0,
                                                int nbn, int nq1) {
    __shared__ __align__(16) char smemBuf[PHASEA_SMEM];
    int b = blockIdx.x, t = threadIdx.x;
    if (b < nbn) {
        float* sW = reinterpret_cast<float*>(smemBuf);
        float* sR = reinterpret_cast<float*>(smemBuf + 96 * 32 * 4);
        node_pre_body(repr_ext, 0, N, b * 128, t, sW, sR);
    } else {
        unsigned long long* sTri = reinterpret_cast<unsigned long long*>(smemBuf);
        float* sRe = reinterpret_cast<float*>(smemBuf + 4352);
        int qb = b - nbn;
        bool l1 = qb < nq1;
        quad_body(l1 ? rel1 : rel0, l1 ? dLogits1 : dLogits0,
                  l1 ? E1 : E0, (l1 ? qb : qb - nq1) * 256, t, sTri, sRe);
    }
}

// ---------------- node precompute standalone (layer 0, mode 1) ----------------
__global__ void __launch_bounds__(128, 6) node_pre3_k(const float* __restrict__ repr_ext,
                                                      int mode, int N) {
    __shared__ __align__(16) float sW[96 * 32];
    __shared__ float sR[128 * 33];
    node_pre_body(repr_ext, mode, N, blockIdx.x * 128, threadIdx.x, sW, sR);
}

// ---------------- linear logit terms: 4 edges per warp, 8 lanes each ----------
__global__ void __launch_bounds__(256) edge_lin4_k(const int* __restrict__ src,
                                                   const int* __restrict__ dst,
                                                   const int* __restrict__ eg,
                                                   const float* __restrict__ rel,
                                                   const float* repr_ext, int use_internal,
                                                   int layer1, int E) {
    const float* repr = use_internal ? dRepr : repr_ext;
    float* lgt = layer1 ? dLogits1 : dLogits0;
    unsigned gid = blockIdx.x * (unsigned)blockDim.x + threadIdx.x;
    int e = (int)(gid >> 3);          // 8 lanes per edge
    int q = (int)(gid & 7);
    bool valid = e < E;
    int ee = valid ? e : 0;
    int s = __ldg(&src[ee]), d = __ldg(&dst[ee]), g = __ldg(&eg[ee]);

    float4 x  = *reinterpret_cast<const float4*>(&repr[s * 32 + q * 4]);
    float4 y  = *reinterpret_cast<const float4*>(&repr[d * 32 + q * 4]);
    float4 zz = *reinterpret_cast<const float4*>(&dZ[d * 32 + q * 4]);
    float4 pp = *reinterpret_cast<const float4*>(&dP[s * 32 + q * 4]);
    float4 tt = *reinterpret_cast<const float4*>(&dT[d * 32 + q * 4]);
    float4 re = ldcs4(&rel[(size_t)ee * 32 + q * 4]);   // single-use stream
    float4 gx = *reinterpret_cast<const float4*>(&dGx[g * 32 + q * 4]);
    float4 gy = *reinterpret_cast<const float4*>(&dGy[g * 32 + q * 4]);
    float4 gr = *reinterpret_cast<const float4*>(&dGrel[g * 32 + q * 4]);

    float part = x.x * (zz.x + gx.x) + x.y * (zz.y + gx.y)
               + x.z * (zz.z + gx.z) + x.w * (zz.w + gx.w);
    part = fmaf(y.x, gy.x, part); part = fmaf(y.y, gy.y, part);
    part = fmaf(y.z, gy.z, part); part = fmaf(y.w, gy.w, part);
    part = fmaf(re.x, pp.x + tt.x + gr.x, part);
    part = fmaf(re.y, pp.y + tt.y + gr.y, part);
    part = fmaf(re.z, pp.z + tt.z + gr.z, part);
    part = fmaf(re.w, pp.w + tt.w + gr.w, part);

    part += __shfl_xor_sync(0xffffffffu, part, 1);
    part += __shfl_xor_sync(0xffffffffu, part, 2);
    part += __shfl_xor_sync(0xffffffffu, part, 4);

    if (valid && q == 0) {
        float logit = part + lgt[e] + dCq[g];
        lgt[e] = logit;
        atomicMax(&dNodeMax[s], encf(logit));
    }
}

// ---------------- exp(logit - max) + per-src sum, split-half 2-edge ILP -------
// Thread i handles edges i and i+H (both halves coalesced per warp).
__global__ void edge_exp_k(const int* __restrict__ src, int layer1, int E) {
    const float* lgt = layer1 ? dLogits1 : dLogits0;
    int H = (E + 1) >> 1;
    int i = blockIdx.x * blockDim.x + threadIdx.x;
    if (i >= H) return;
    int eA = i, eB = i + H;
    bool hasB = eB < E;
    int sA = src[eA];
    int sB = hasB ? src[eB] : 0;
    float lgA = lgt[eA];
    float lgB = hasB ? lgt[eB] : 0.f;
    float mA = decf(dNodeMax[sA]);
    float mB = hasB ? decf(dNodeMax[sB]) : 0.f;
    float exA = __expf(lgA - mA);
    float exB = __expf(lgB - mB);
    dEx[eA] = exA;
    atomicAdd(&dNodeSum[sA], exA);
    if (hasB) {
        dEx[eB] = exB;
        atomicAdd(&dNodeSum[sB], exB);
    }
}

// ---------------- normalize + encoded target score (layer 1), split-half ------
__global__ void ts_k(const int* __restrict__ src, const float* __restrict__ vscore, int E) {
    int H = (E + 1) >> 1;
    int i = blockIdx.x * blockDim.x + threadIdx.x;
    if (i >= H) return;
    int eA = i, eB = i + H;
    bool hasB = eB < E;
    int sA = src[eA];
    int sB = hasB ? src[eB] : 0;
    float exA = dEx[eA];
    float exB = hasB ? dEx[eB] : 0.f;
    float sumA = dNodeSum[sA];
    float sumB = hasB ? dNodeSum[sB] : 1.f;
    float vsA = vscore[sA];
    float vsB = hasB ? vscore[sB] : 0.f;
    float wA = __fdividef(exA, sumA);
    float wB = __fdividef(exB, sumB);
    dEx[eA] = wA;
    dTsEnc[eA] = __float_as_uint(wA * vsA);
    if (hasB) {
        dEx[eB] = wB;
        dTsEnc[eB] = __float_as_uint(wB * vsB);
    }
}

// ---------------- per-group top-k (stable: value desc, index asc), 512 thr ----
__global__ void __launch_bounds__(512) topk_k(const int* maxe) {
    int g = blockIdx.x;
    int lo = dOff[g], hi = dOff[g + 1];
    int len = hi - lo;
    if (len <= 0) return;
    int K = maxe ? maxe[0] : 500;
    if (K > len) K = len;

    __shared__ int hist[256];
    __shared__ int s_selbin, s_rem;
    unsigned prefix = 0u;
    int remaining = K;
    for (int shift = 24; shift >= 0; shift -= 8) {
        unsigned mask_hi = (shift == 24) ? 0u : (0xFFFFFFFFu << (shift + 8));
        for (int i = threadIdx.x; i < 256; i += blockDim.x) hist[i] = 0;
        __syncthreads();
        for (int i = lo + threadIdx.x; i < hi; i += blockDim.x) {
            unsigned v = dTsEnc[i];
            if ((v & mask_hi) == prefix) atomicAdd(&hist[(v >> shift) & 255], 1);
        }
        __syncthreads();
        if (threadIdx.x == 0) {
            int cum = 0, b = 255;
            for (; b > 0; b--) { cum += hist[b]; if (cum >= remaining) break; }
            if (cum < remaining) cum += hist[0];
            s_selbin = b;
            s_rem = remaining - (cum - hist[b]);
        }
        __syncthreads();
        prefix |= ((unsigned)s_selbin) << shift;
        remaining = s_rem;
        __syncthreads();
    }
    unsigned T = prefix;
    int quota_eq = remaining;

    __shared__ int warp_cnt[16];
    __shared__ int s_running;
    if (threadIdx.x == 0) s_running = 0;
    __syncthreads();
    for (int base = lo; base < hi; base += blockDim.x) {
        int i = base + (int)threadIdx.x;
        bool valid = i < hi;
        unsigned v = valid ? dTsEnc[i] : 0u;
        bool gt = valid && (v > T);
        bool eq = valid && (v == T);
        unsigned bal = __ballot_sync(0xffffffffu, eq);
        int lane = threadIdx.x & 31, wrp = threadIdx.x >> 5;
        int myrank = __popc(bal & ((1u << lane) - 1u));
        if (lane == 0) warp_cnt[wrp] = __popc(bal);
        __syncthreads();
        int woff = 0, chunk_tot = 0;
        #pragma unroll
        for (int ww = 0; ww < 16; ww++) {
            int c = warp_cnt[ww];
            if (ww < wrp) woff += c;
            chunk_tot += c;
        }
        int rank = s_running + woff + myrank;
        bool keep = gt || (eq && rank < quota_eq);
        if (keep) {
            int pos = atomicAdd(&dKcount, 1);
            dKlist[pos] = i;
        }
        __syncthreads();
        if (threadIdx.x == 0) s_running += chunk_tot;
        __syncthreads();
    }
}

// ---------------- layer-1 scatter (kept edges), 8 thr/edge, grid-stride -------
__global__ void scatter1_k(const int* __restrict__ src, const int* __restrict__ dst,
                           const float* __restrict__ node_repr, const float* __restrict__ vscore,
                           float* __restrict__ score_out) {
    unsigned gid = blockIdx.x * (unsigned)blockDim.x + threadIdx.x;
    int q = (int)(gid & 7);
    int stride = (int)((gridDim.x * (unsigned)blockDim.x) >> 3);
    int total = dKcount;
    for (int i = (int)(gid >> 3); i < total; i += stride) {
        int e = dKlist[i];
        int s = src[e], d = dst[e];
        float w = dEx[e];
        float4 v = *reinterpret_cast<const float4*>(&node_repr[s * 32 + q * 4]);
        red4(&dAgg[d * 32 + q * 4], w * v.x, w * v.y, w * v.z, w * v.w);
        if (q == 0) atomicAdd(&score_out[d], w * vscore[s]);
    }
}

// ---------------- layer-0 scatter (all edges), fused normalize ----------------
__global__ void scatter0_k(const int* __restrict__ src, const int* __restrict__ dst, int E) {
    unsigned gid = blockIdx.x * (unsigned)blockDim.x + threadIdx.x;
    int e = (int)(gid >> 3), q = (int)(gid & 7);
    if (e >= E) return;
    int s = src[e], d = dst[e];
    float w = __fdividef(dEx[e], dNodeSum[s]);
    float4 v = *reinterpret_cast<const float4*>(&dRepr[s * 32 + q * 4]);
    red4(&dAgg[d * 32 + q * 4], w * v.x, w * v.y, w * v.z, w * v.w);
}

// ---------------- final bypass: LeakyReLU(Wlin r2 + blin) ---------------------
__global__ void __launch_bounds__(128, 6) final3_k(const float* __restrict__ Wlin,
                                                   const float* __restrict__ blin,
                                                   float* __restrict__ out_repr, int N) {
    __shared__ __align__(16) float sW[1024];
    __shared__ float sR[128 * 33];
    __shared__ float sB[32];
    int t = threadIdx.x;
    for (int i = t; i < 1024; i += 128) sW[i] = Wlin[i];
    if (t < 32) sB[t] = blin[t];
    int base = blockIdx.x * 128;
    for (int i = t; i < 128 * 32; i += 128) {
        int n = base + (i >> 5);
        float v = 0.f;
        if (n < N) {
            int g = n * 32 + (i & 31);
            v = fmaf(0.8f, dAgg[g], 0.2f * dRepr[g]);
        }
        sR[(i >> 5) * 33 + (i & 31)] = v;
    }
    __syncthreads();
    float re[32];
    #pragma unroll
    for (int k = 0; k < 32; k++) re[k] = sR[t * 33 + k];
    const float4* Wv = reinterpret_cast<const float4*>(sW);
    bool live = (base + t) < N;
    #pragma unroll 1
    for (int h = 0; h < 2; h++) {
        float acc[16];
        #pragma unroll
        for (int o = 0; o < 16; o++) {
            int row = h * 16 + o;
            float a = sB[row];
            #pragma unroll
            for (int k4 = 0; k4 < 8; k4++) {
                float4 m = Wv[row * 8 + k4];
                a = fmaf(m.x, re[4 * k4 + 0], a);
                a = fmaf(m.y, re[4 * k4 + 1], a);
                a = fmaf(m.z, re[4 * k4 + 2], a);
                a = fmaf(m.w, re[4 * k4 + 3], a);
            }
            acc[o] = (a >= 0.f) ? a : 0.01f * a;
        }
        __syncthreads();
        if (live) {
            #pragma unroll
            for (int o = 0; o < 16; o++) sR[t * 17 + o] = acc[o];
        }
        __syncthreads();
        for (int i = t; i < 128 * 16; i += 128) {
            int n = base + (i >> 4);
            if (n < N) out_repr[n * 32 + h * 16 + (i & 15)] = sR[(i >> 4) * 17 + (i & 15)];
        }
    }
}

// ---------------- launcher ----------------------------------------------------
extern "C" void kernel_launch(void* const* d_in, const int* in_sizes, int n_in,
                              void* d_out, int out_size) {
    const float* vscore    = (const float*)d_in[0];
    const float* node_repr = (const float*)d_in[1];
    const int*   eg0       = (const int*)d_in[2];
    const int*   src0      = (const int*)d_in[3];
    const int*   dst0      = (const int*)d_in[4];
    const float* rel0      = (const float*)d_in[5];
    const int*   eg1       = (const int*)d_in[6];
    const int*   src1      = (const int*)d_in[7];
    const int*   dst1      = (const int*)d_in[8];
    const float* rel1      = (const float*)d_in[9];
    const float* qemb      = (const float*)d_in[10];
    const float* remb      = (const float*)d_in[11];
    const float* Wq        = (const float*)d_in[12];
    const float* Wk        = (const float*)d_in[13];
    const float* Wlin      = (const float*)d_in[14];
    const float* blin      = (const float*)d_in[15];
    const int*   maxep     = (n_in > 16) ? (const int*)d_in[16] : nullptr;

    int N  = in_sizes[0];
    int E0 = in_sizes[2];
    int E1 = in_sizes[6];
    int Q  = in_sizes[10] / 32;

    float* out_score = (float*)d_out;
    float* out_repr  = (float*)d_out + N;

    int nbn  = (N + 127) / 128;
    int nq0  = (E0 + 255) / 256;            // 256 edges per quad block
    int nq1  = (E1 + 255) / 256;
    int ebl0 = (E0 * 8 + 255) / 256;        // 8 lanes/edge
    int ebl1 = (E1 * 8 + 255) / 256;
    int ebh0 = ((E0 + 1) / 2 + 255) / 256;  // split-half: H threads
    int ebh1 = ((E1 + 1) / 2 + 255) / 256;
    int nrst = (N * 32 + 127) / 128;

    // ---- prep: M, per-query vectors, group offsets, resets ----
    prep_k<<<129 + Q + nrst, 128>>>(Wq, Wk, qemb, remb, eg1, out_score, N, E1, Q);

    // ---- phase A (merged): node_pre(layer-1 input) + quad for BOTH layers ----
    phaseA_k<<<nbn + nq1 + nq0, 128>>>(node_repr, rel1, rel0, N, E1, E0, nbn, nq1);

    // ---- layer 1 (pruned) ----
    edge_lin4_k<<<ebl1, 256>>>(src1, dst1, eg1, rel1, node_repr, 0, 1, E1);
    edge_exp_k<<<ebh1, 256>>>(src1, 1, E1);
    ts_k<<<ebh1, 256>>>(src1, vscore, E1);
    topk_k<<<Q, 512>>>(maxep);
    scatter1_k<<<2000, 256>>>(src1, dst1, node_repr, vscore, out_score);

    // ---- layer 0 (no pruning); node_pre fuses repr update + resets ----
    node_pre3_k<<<nbn, 128>>>(node_repr, 1, N);
    edge_lin4_k<<<ebl0, 256>>>(src0, dst0, eg0, rel0, nullptr, 1, 0, E0);
    edge_exp_k<<<ebh0, 256>>>(src0, 0, E0);
    scatter0_k<<<ebl0, 256>>>(src0, dst0, E0);

    // ---- bypass_forward ----
    final3_k<<<nbn, 128>>>(Wlin, blin, out_repr, N);
}

// round 16
// speedup vs baseline: 1.0005x; 1.0005x over previous
#include <cuda_runtime.h>

// ---------------- problem-size capacities (fixed by dataset) ----------------
static const int NMAX  = 100000;
static const int EMAX  = 500000;
static const int QMAXC = 128;

// ---------------- device scratch (static; no allocation) --------------------
__device__ float    dM[128 * 128];          // M = Wq^T @ Wk
__device__ float    dGx[QMAXC * 32];
__device__ float    dGy[QMAXC * 32];
__device__ float    dGrel[QMAXC * 32];
__device__ float    dCq[QMAXC];
__device__ float    dZ[NMAX * 32];
__device__ float    dP[NMAX * 32];
__device__ float    dT[NMAX * 32];
__device__ float    dRepr[NMAX * 32];
__device__ float    dAgg[NMAX * 32];
__device__ float    dLogits1[EMAX];         // layer-1: quad term, then logit
__device__ float    dLogits0[EMAX];         // layer-0: quad term, then logit
__device__ float    dEx[EMAX];              // exp, then normalized w
__device__ unsigned dTsEnc[EMAX];
__device__ unsigned dNodeMax[NMAX];
__device__ float    dNodeSum[NMAX];
__device__ int      dOff[QMAXC + 1];
__device__ int      dKlist[EMAX];
__device__ int      dKcount;

// ---------------- helpers ----------------------------------------------------
__device__ __forceinline__ unsigned encf(float f) {
    unsigned u = __float_as_uint(f);
    return (u & 0x80000000u) ? ~u : (u | 0x80000000u);
}
__device__ __forceinline__ float decf(unsigned e) {
    unsigned u = (e & 0x80000000u) ? (e & 0x7FFFFFFFu) : ~e;
    return __uint_as_float(u);
}
__device__ __forceinline__ unsigned long long packf2(float lo, float hi) {
    unsigned long long r;
    asm("mov.b64 %0, {%1, %2};" : "=l"(r) : "f"(lo), "f"(hi));
    return r;
}
__device__ __forceinline__ void unpackf2(unsigned long long v, float& lo, float& hi) {
    asm("mov.b64 {%0, %1}, %2;" : "=f"(lo), "=f"(hi) : "l"(v));
}
__device__ __forceinline__ unsigned long long fmaf2(unsigned long long a, unsigned long long b,
                                                    unsigned long long c) {
    unsigned long long d;
    asm("fma.rn.f32x2 %0, %1, %2, %3;" : "=l"(d) : "l"(a), "l"(b), "l"(c));
    return d;
}
__device__ __forceinline__ void red4(float* p, float a, float b, float c, float d) {
    asm volatile("red.global.v4.f32.add [%0], {%1, %2, %3, %4};"
                 :: "l"(p), "f"(a), "f"(b), "f"(c), "f"(d) : "memory");
}
// streaming (evict-first) vector load: for single-use data
__device__ __forceinline__ float4 ldcs4(const float* p) {
    float4 v;
    asm volatile("ld.global.cs.v4.f32 {%0, %1, %2, %3}, [%4];"
                 : "=f"(v.x), "=f"(v.y), "=f"(v.z), "=f"(v.w) : "l"(p));
    return v;
}

// ---------------- prep: computeM + query_pre + group_off + resets -------------
__global__ void __launch_bounds__(128) prep_k(const float* __restrict__ Wq,
                                              const float* __restrict__ Wk,
                                              const float* __restrict__ qemb,
                                              const float* __restrict__ remb,
                                              const int* __restrict__ eg1,
                                              float* __restrict__ score_out,
                                              int N, int E1, int Q) {
    int b = blockIdx.x, t = threadIdx.x;
    if (b < 128) {
        int i = b, j = t;
        float acc = 0.f;
        #pragma unroll 8
        for (int o = 0; o < 128; o++)
            acc = fmaf(__ldg(&Wq[o * 128 + i]), __ldg(&Wk[o * 128 + j]), acc);
        dM[i * 128 + j] = acc;
        return;
    }
    if (b < 128 + Q) {
        if (t >= 32) return;
        int q = b - 128, d = t;
        __shared__ float qv[32], rv[32];
        qv[d] = qemb[q * 32 + d];
        rv[d] = remb[q * 32 + d];
        __syncwarp();
        __shared__ float su[128], sv[128];
        for (int o = d; o < 128; o += 32) {
            float uu = 0.f, vv = 0.f;
            #pragma unroll
            for (int c = 0; c < 32; c++) {
                uu = fmaf(__ldg(&Wk[o * 128 + 64 + c]), qv[c], uu);
                uu = fmaf(__ldg(&Wk[o * 128 + 96 + c]), rv[c], uu);
                vv = fmaf(__ldg(&Wq[o * 128 + 64 + c]), qv[c], vv);
                vv = fmaf(__ldg(&Wq[o * 128 + 96 + c]), rv[c], vv);
            }
            su[o] = uu; sv[o] = vv;
        }
        __syncwarp();
        float gx = 0.f, gy = 0.f, gr = 0.f, cq = 0.f;
        for (int o = 0; o < 128; o++) {
            float uo = su[o], vo = sv[o];
            gx = fmaf(__ldg(&Wq[o * 128 + d]), uo, gx);
            gy = fmaf(__ldg(&Wk[o * 128 + d]), vo, gy);
            gr = fmaf(__ldg(&Wq[o * 128 + 32 + d]), uo, gr);
            gr = fmaf(__ldg(&Wk[o * 128 + 32 + d]), vo, gr);
            if (d == 0) cq = fmaf(uo, vo, cq);
        }
        dGx[q * 32 + d] = gx;
        dGy[q * 32 + d] = gy;
        dGrel[q * 32 + d] = gr;
        if (d == 0) dCq[q] = cq;
        return;
    }
    if (b == 128 + Q) {
        for (int g = t; g <= Q; g += 128) {
            int lo = 0, hi = E1;
            while (lo < hi) {
                int mid = (lo + hi) >> 1;
                if (eg1[mid] < g) lo = mid + 1; else hi = mid;
            }
            dOff[g] = lo;
        }
        return;
    }
    // resets: float4-vectorized dAgg zeroing; per-node scalars alongside
    int i = (b - (129 + Q)) * 128 + t;             // float4 index over dAgg
    if (i < N * 8)
        reinterpret_cast<float4*>(dAgg)[i] = make_float4(0.f, 0.f, 0.f, 0.f);
    if (i < N) {
        dNodeMax[i] = 0u;
        dNodeSum[i] = 0.f;
        score_out[i] = 0.f;
    }
    if (i == 0) dKcount = 0;
}

// ---------------- device bodies: node precompute / quad -----------------------
// node body: 128 threads, 128 nodes. sW: 96*32 floats, sR: 128*33 floats.
__device__ __forceinline__ void node_pre_body(const float* __restrict__ repr_ext,
                                              int mode, int N, int base, int t,
                                              float* sW, float* sR) {
    for (int i = t; i < 96 * 32; i += 128) {
        int o = i >> 5, k = i & 31;
        float v;
        if (o < 32)      v = dM[o * 128 + k];
        else if (o < 64) v = dM[k * 128 + 32 + (o - 32)];
        else             v = dM[(32 + (o - 64)) * 128 + k];
        sW[i] = v;
    }
    if (mode == 0) {
        for (int i = t; i < 128 * 32; i += 128) {
            int n = base + (i >> 5);
            sR[(i >> 5) * 33 + (i & 31)] = (n < N) ? repr_ext[n * 32 + (i & 31)] : 0.f;
        }
    } else {
        for (int i = t; i < 128 * 32; i += 128) {
            int n = base + (i >> 5);
            float v = 0.f;
            if (n < N) {
                int g = n * 32 + (i & 31);
                v = fmaf(0.8f, dAgg[g], 0.2f * repr_ext[g]);
                dRepr[g] = v;
                dAgg[g] = 0.f;
            }
            sR[(i >> 5) * 33 + (i & 31)] = v;
        }
        int n = base + t;
        if (n < N) { dNodeMax[n] = 0u; dNodeSum[n] = 0.f; }
    }
    __syncthreads();
    float re[32];
    #pragma unroll
    for (int k = 0; k < 32; k++) re[k] = sR[t * 33 + k];

    const float4* Wv = reinterpret_cast<const float4*>(sW);
    bool live = (base + t) < N;
    #pragma unroll 1
    for (int c = 0; c < 3; c++) {
        float* out = (c == 0) ? dZ : (c == 1) ? dP : dT;
        #pragma unroll 1
        for (int h = 0; h < 2; h++) {
            float acc[16];
            #pragma unroll
            for (int o = 0; o < 16; o++) {
                int row = c * 32 + h * 16 + o;
                float a = 0.f;
                #pragma unroll
                for (int k4 = 0; k4 < 8; k4++) {
                    float4 m = Wv[row * 8 + k4];
                    a = fmaf(m.x, re[4 * k4 + 0], a);
                    a = fmaf(m.y, re[4 * k4 + 1], a);
                    a = fmaf(m.z, re[4 * k4 + 2], a);
                    a = fmaf(m.w, re[4 * k4 + 3], a);
                }
                acc[o] = a;
            }
            __syncthreads();
            if (live) {
                #pragma unroll
                for (int o = 0; o < 16; o++) sR[t * 17 + o] = acc[o];
            }
            __syncthreads();
            for (int i = t; i < 128 * 16; i += 128) {
                int n = base + (i >> 4);
                if (n < N) out[n * 32 + h * 16 + (i & 15)] = sR[(i >> 4) * 17 + (i & 15)];
            }
        }
    }
}

// quad body: 128 threads, 256 edges (2/thread via f32x2). sTri: 528 u64,
// sRe: 128*33 floats. rel read with streaming hint (single-use).
__device__ __forceinline__ void quad_body(const float* __restrict__ rel,
                                          float* __restrict__ out, int E,
                                          int base, int t,
                                          unsigned long long* sTri, float* sRe) {
    for (int i = t; i < 528; i += 128) {
        int j = 0, off = 0;
        while (off + (32 - j) <= i) { off += 32 - j; j++; }
        int k = j + (i - off);
        float v = (k == j) ? dM[(32 + j) * 128 + 32 + j]
                           : dM[(32 + j) * 128 + 32 + k] + dM[(32 + k) * 128 + 32 + j];
        sTri[i] = packf2(v, v);
    }
    // stage A: 128 edges (streaming loads)
    for (int i = t; i < 128 * 8; i += 128) {
        int erow = i >> 3, c4 = i & 7;
        int e = base + erow;
        float4 v = (e < E) ? ldcs4(&rel[(size_t)e * 32 + c4 * 4])
                           : make_float4(0.f, 0.f, 0.f, 0.f);
        sRe[erow * 33 + c4 * 4 + 0] = v.x;
        sRe[erow * 33 + c4 * 4 + 1] = v.y;
        sRe[erow * 33 + c4 * 4 + 2] = v.z;
        sRe[erow * 33 + c4 * 4 + 3] = v.w;
    }
    __syncthreads();
    float reA[32];
    #pragma unroll
    for (int k = 0; k < 32; k++) reA[k] = sRe[t * 33 + k];
    __syncthreads();
    for (int i = t; i < 128 * 8; i += 128) {
        int erow = i >> 3, c4 = i & 7;
        int e = base + 128 + erow;
        float4 v = (e < E) ? ldcs4(&rel[(size_t)e * 32 + c4 * 4])
                           : make_float4(0.f, 0.f, 0.f, 0.f);
        sRe[erow * 33 + c4 * 4 + 0] = v.x;
        sRe[erow * 33 + c4 * 4 + 1] = v.y;
        sRe[erow * 33 + c4 * 4 + 2] = v.z;
        sRe[erow * 33 + c4 * 4 + 3] = v.w;
    }
    __syncthreads();
    unsigned long long re2[32];
    #pragma unroll
    for (int k = 0; k < 32; k++) re2[k] = packf2(reA[k], sRe[t * 33 + k]);

    const unsigned long long z2 = packf2(0.f, 0.f);
    unsigned long long w2 = z2;
    #pragma unroll
    for (int j = 0; j < 32; j++) {
        const int off = 32 * j - (j * (j - 1)) / 2;
        unsigned long long v2 = fmaf2(sTri[off], re2[j], z2);
        #pragma unroll
        for (int k = j + 1; k < 32; k++)
            v2 = fmaf2(sTri[off + (k - j)], re2[k], v2);
        w2 = fmaf2(re2[j], v2, w2);
    }
    float wA, wB;
    unpackf2(w2, wA, wB);
    int eA = base + t, eB = base + 128 + t;
    if (eA < E) out[eA] = wA;
    if (eB < E) out[eB] = wB;
}

// ---------------- phase A: node_pre(mode 0) + quad(layer1) + quad(layer0) -----
static const int PHASEA_SMEM = 96 * 32 * 4 + 128 * 33 * 4;   // 29184 bytes
__global__ void __launch_bounds__(128) phaseA_k(const float* __restrict__ repr_ext,
                                                const float* __restrict__ rel1,
                                                const float* __restrict__ rel0,
                                                int N, int E1, int E0,
                                                int nbn, int nq1) {
    __shared__ __align__(16) char smemBuf[PHASEA_SMEM];
    int b = blockIdx.x, t = threadIdx.x;
    if (b < nbn) {
        float* sW = reinterpret_cast<float*>(smemBuf);
        float* sR = reinterpret_cast<float*>(smemBuf + 96 * 32 * 4);
        node_pre_body(repr_ext, 0, N, b * 128, t, sW, sR);
    } else {
        unsigned long long* sTri = reinterpret_cast<unsigned long long*>(smemBuf);
        float* sRe = reinterpret_cast<float*>(smemBuf + 4352);
        int qb = b - nbn;
        bool l1 = qb < nq1;
        quad_body(l1 ? rel1 : rel0, l1 ? dLogits1 : dLogits0,
                  l1 ? E1 : E0, (l1 ? qb : qb - nq1) * 256, t, sTri, sRe);
    }
}

// ---------------- node precompute standalone (layer 0, mode 1) ----------------
__global__ void __launch_bounds__(128, 6) node_pre3_k(const float* __restrict__ repr_ext,
                                                      int mode, int N) {
    __shared__ __align__(16) float sW[96 * 32];
    __shared__ float sR[128 * 33];
    node_pre_body(repr_ext, mode, N, blockIdx.x * 128, threadIdx.x, sW, sR);
}

// ---------------- linear logit terms: 4 edges per warp, 8 lanes each ----------
__global__ void __launch_bounds__(256) edge_lin4_k(const int* __restrict__ src,
                                                   const int* __restrict__ dst,
                                                   const int* __restrict__ eg,
                                                   const float* __restrict__ rel,
                                                   const float* repr_ext, int use_internal,
                                                   int layer1, int E) {
    const float* repr = use_internal ? dRepr : repr_ext;
    float* lgt = layer1 ? dLogits1 : dLogits0;
    unsigned gid = blockIdx.x * (unsigned)blockDim.x + threadIdx.x;
    int e = (int)(gid >> 3);          // 8 lanes per edge
    int q = (int)(gid & 7);
    bool valid = e < E;
    int ee = valid ? e : 0;
    int s = __ldg(&src[ee]), d = __ldg(&dst[ee]), g = __ldg(&eg[ee]);

    float4 x  = *reinterpret_cast<const float4*>(&repr[s * 32 + q * 4]);
    float4 y  = *reinterpret_cast<const float4*>(&repr[d * 32 + q * 4]);
    float4 zz = *reinterpret_cast<const float4*>(&dZ[d * 32 + q * 4]);
    float4 pp = *reinterpret_cast<const float4*>(&dP[s * 32 + q * 4]);
    float4 tt = *reinterpret_cast<const float4*>(&dT[d * 32 + q * 4]);
    float4 re = ldcs4(&rel[(size_t)ee * 32 + q * 4]);   // single-use stream
    float4 gx = *reinterpret_cast<const float4*>(&dGx[g * 32 + q * 4]);
    float4 gy = *reinterpret_cast<const float4*>(&dGy[g * 32 + q * 4]);
    float4 gr = *reinterpret_cast<const float4*>(&dGrel[g * 32 + q * 4]);

    float part = x.x * (zz.x + gx.x) + x.y * (zz.y + gx.y)
               + x.z * (zz.z + gx.z) + x.w * (zz.w + gx.w);
    part = fmaf(y.x, gy.x, part); part = fmaf(y.y, gy.y, part);
    part = fmaf(y.z, gy.z, part); part = fmaf(y.w, gy.w, part);
    part = fmaf(re.x, pp.x + tt.x + gr.x, part);
    part = fmaf(re.y, pp.y + tt.y + gr.y, part);
    part = fmaf(re.z, pp.z + tt.z + gr.z, part);
    part = fmaf(re.w, pp.w + tt.w + gr.w, part);

    part += __shfl_xor_sync(0xffffffffu, part, 1);
    part += __shfl_xor_sync(0xffffffffu, part, 2);
    part += __shfl_xor_sync(0xffffffffu, part, 4);

    if (valid && q == 0) {
        float logit = part + lgt[e] + dCq[g];
        lgt[e] = logit;
        atomicMax(&dNodeMax[s], encf(logit));
    }
}

// ---------------- exp(logit - max) + per-src sum -------------------------------
__global__ void edge_exp_k(const int* __restrict__ src, int layer1, int E) {
    int e = blockIdx.x * blockDim.x + threadIdx.x;
    if (e >= E) return;
    int s = src[e];
    float m = decf(dNodeMax[s]);
    float lg = layer1 ? dLogits1[e] : dLogits0[e];
    float ex = __expf(lg - m);
    dEx[e] = ex;
    atomicAdd(&dNodeSum[s], ex);
}

// ---------------- normalize + encoded target score (layer 1) ------------------
__global__ void ts_k(const int* __restrict__ src, const float* __restrict__ vscore, int E) {
    int e = blockIdx.x * blockDim.x + threadIdx.x;
    if (e >= E) return;
    int s = src[e];
    float w = __fdividef(dEx[e], dNodeSum[s]);
    dEx[e] = w;
    dTsEnc[e] = __float_as_uint(w * vscore[s]);
}

// ---------------- per-group top-k (stable: value desc, index asc), 512 thr ----
__global__ void __launch_bounds__(512) topk_k(const int* maxe) {
    int g = blockIdx.x;
    int lo = dOff[g], hi = dOff[g + 1];
    int len = hi - lo;
    if (len <= 0) return;
    int K = maxe ? maxe[0] : 500;
    if (K > len) K = len;

    __shared__ int hist[256];
    __shared__ int s_selbin, s_rem;
    unsigned prefix = 0u;
    int remaining = K;
    for (int shift = 24; shift >= 0; shift -= 8) {
        unsigned mask_hi = (shift == 24) ? 0u : (0xFFFFFFFFu << (shift + 8));
        for (int i = threadIdx.x; i < 256; i += blockDim.x) hist[i] = 0;
        __syncthreads();
        for (int i = lo + threadIdx.x; i < hi; i += blockDim.x) {
            unsigned v = dTsEnc[i];
            if ((v & mask_hi) == prefix) atomicAdd(&hist[(v >> shift) & 255], 1);
        }
        __syncthreads();
        if (threadIdx.x == 0) {
            int cum = 0, b = 255;
            for (; b > 0; b--) { cum += hist[b]; if (cum >= remaining) break; }
            if (cum < remaining) cum += hist[0];
            s_selbin = b;
            s_rem = remaining - (cum - hist[b]);
        }
        __syncthreads();
        prefix |= ((unsigned)s_selbin) << shift;
        remaining = s_rem;
        __syncthreads();
    }
    unsigned T = prefix;
    int quota_eq = remaining;

    __shared__ int warp_cnt[16];
    __shared__ int s_running;
    if (threadIdx.x == 0) s_running = 0;
    __syncthreads();
    for (int base = lo; base < hi; base += blockDim.x) {
        int i = base + (int)threadIdx.x;
        bool valid = i < hi;
        unsigned v = valid ? dTsEnc[i] : 0u;
        bool gt = valid && (v > T);
        bool eq = valid && (v == T);
        unsigned bal = __ballot_sync(0xffffffffu, eq);
        int lane = threadIdx.x & 31, wrp = threadIdx.x >> 5;
        int myrank = __popc(bal & ((1u << lane) - 1u));
        if (lane == 0) warp_cnt[wrp] = __popc(bal);
        __syncthreads();
        int woff = 0, chunk_tot = 0;
        #pragma unroll
        for (int ww = 0; ww < 16; ww++) {
            int c = warp_cnt[ww];
            if (ww < wrp) woff += c;
            chunk_tot += c;
        }
        int rank = s_running + woff + myrank;
        bool keep = gt || (eq && rank < quota_eq);
        if (keep) {
            int pos = atomicAdd(&dKcount, 1);
            dKlist[pos] = i;
        }
        __syncthreads();
        if (threadIdx.x == 0) s_running += chunk_tot;
        __syncthreads();
    }
}

// ---------------- layer-1 scatter (kept edges), 8 thr/edge, grid-stride -------
__global__ void scatter1_k(const int* __restrict__ src, const int* __restrict__ dst,
                           const float* __restrict__ node_repr, const float* __restrict__ vscore,
                           float* __restrict__ score_out) {
    unsigned gid = blockIdx.x * (unsigned)blockDim.x + threadIdx.x;
    int q = (int)(gid & 7);
    int stride = (int)((gridDim.x * (unsigned)blockDim.x) >> 3);
    int total = dKcount;
    for (int i = (int)(gid >> 3); i < total; i += stride) {
        int e = dKlist[i];
        int s = src[e], d = dst[e];
        float w = dEx[e];
        float4 v = *reinterpret_cast<const float4*>(&node_repr[s * 32 + q * 4]);
        red4(&dAgg[d * 32 + q * 4], w * v.x, w * v.y, w * v.z, w * v.w);
        if (q == 0) atomicAdd(&score_out[d], w * vscore[s]);
    }
}

// ---------------- layer-0 scatter (all edges), fused normalize ----------------
__global__ void scatter0_k(const int* __restrict__ src, const int* __restrict__ dst, int E) {
    unsigned gid = blockIdx.x * (unsigned)blockDim.x + threadIdx.x;
    int e = (int)(gid >> 3), q = (int)(gid & 7);
    if (e >= E) return;
    int s = src[e], d = dst[e];
    float w = __fdividef(dEx[e], dNodeSum[s]);
    float4 v = *reinterpret_cast<const float4*>(&dRepr[s * 32 + q * 4]);
    red4(&dAgg[d * 32 + q * 4], w * v.x, w * v.y, w * v.z, w * v.w);
}

// ---------------- final bypass: LeakyReLU(Wlin r2 + blin) ---------------------
__global__ void __launch_bounds__(128, 6) final3_k(const float* __restrict__ Wlin,
                                                   const float* __restrict__ blin,
                                                   float* __restrict__ out_repr, int N) {
    __shared__ __align__(16) float sW[1024];
    __shared__ float sR[128 * 33];
    __shared__ float sB[32];
    int t = threadIdx.x;
    for (int i = t; i < 1024; i += 128) sW[i] = Wlin[i];
    if (t < 32) sB[t] = blin[t];
    int base = blockIdx.x * 128;
    for (int i = t; i < 128 * 32; i += 128) {
        int n = base + (i >> 5);
        float v = 0.f;
        if (n < N) {
            int g = n * 32 + (i & 31);
            v = fmaf(0.8f, dAgg[g], 0.2f * dRepr[g]);
        }
        sR[(i >> 5) * 33 + (i & 31)] = v;
    }
    __syncthreads();
    float re[32];
    #pragma unroll
    for (int k = 0; k < 32; k++) re[k] = sR[t * 33 + k];
    const float4* Wv = reinterpret_cast<const float4*>(sW);
    bool live = (base + t) < N;
    #pragma unroll 1
    for (int h = 0; h < 2; h++) {
        float acc[16];
        #pragma unroll
        for (int o = 0; o < 16; o++) {
            int row = h * 16 + o;
            float a = sB[row];
            #pragma unroll
            for (int k4 = 0; k4 < 8; k4++) {
                float4 m = Wv[row * 8 + k4];
                a = fmaf(m.x, re[4 * k4 + 0], a);
                a = fmaf(m.y, re[4 * k4 + 1], a);
                a = fmaf(m.z, re[4 * k4 + 2], a);
                a = fmaf(m.w, re[4 * k4 + 3], a);
            }
            acc[o] = (a >= 0.f) ? a : 0.01f * a;
        }
        __syncthreads();
        if (live) {
            #pragma unroll
            for (int o = 0; o < 16; o++) sR[t * 17 + o] = acc[o];
        }
        __syncthreads();
        for (int i = t; i < 128 * 16; i += 128) {
            int n = base + (i >> 4);
            if (n < N) out_repr[n * 32 + h * 16 + (i & 15)] = sR[(i >> 4) * 17 + (i & 15)];
        }
    }
}

// ---------------- launcher ----------------------------------------------------
extern "C" void kernel_launch(void* const* d_in, const int* in_sizes, int n_in,
                              void* d_out, int out_size) {
    const float* vscore    = (const float*)d_in[0];
    const float* node_repr = (const float*)d_in[1];
    const int*   eg0       = (const int*)d_in[2];
    const int*   src0      = (const int*)d_in[3];
    const int*   dst0      = (const int*)d_in[4];
    const float* rel0      = (const float*)d_in[5];
    const int*   eg1       = (const int*)d_in[6];
    const int*   src1      = (const int*)d_in[7];
    const int*   dst1      = (const int*)d_in[8];
    const float* rel1      = (const float*)d_in[9];
    const float* qemb      = (const float*)d_in[10];
    const float* remb      = (const float*)d_in[11];
    const float* Wq        = (const float*)d_in[12];
    const float* Wk        = (const float*)d_in[13];
    const float* Wlin      = (const float*)d_in[14];
    const float* blin      = (const float*)d_in[15];
    const int*   maxep     = (n_in > 16) ? (const int*)d_in[16] : nullptr;

    int N  = in_sizes[0];
    int E0 = in_sizes[2];
    int E1 = in_sizes[6];
    int Q  = in_sizes[10] / 32;

    float* out_score = (float*)d_out;
    float* out_repr  = (float*)d_out + N;

    int nbn  = (N + 127) / 128;
    int nq0  = (E0 + 255) / 256;            // 256 edges per quad block
    int nq1  = (E1 + 255) / 256;
    int ebl0 = (E0 * 8 + 255) / 256;        // 8 lanes/edge
    int ebl1 = (E1 * 8 + 255) / 256;
    int ebt0 = (E0 + 255) / 256;
    int ebt1 = (E1 + 255) / 256;
    int nrst = (N * 8 + 127) / 128;         // float4 resets over dAgg

    // ---- prep: M, per-query vectors, group offsets, resets ----
    prep_k<<<129 + Q + nrst, 128>>>(Wq, Wk, qemb, remb, eg1, out_score, N, E1, Q);

    // ---- phase A (merged): node_pre(layer-1 input) + quad for BOTH layers ----
    phaseA_k<<<nbn + nq1 + nq0, 128>>>(node_repr, rel1, rel0, N, E1, E0, nbn, nq1);

    // ---- layer 1 (pruned) ----
    edge_lin4_k<<<ebl1, 256>>>(src1, dst1, eg1, rel1, node_repr, 0, 1, E1);
    edge_exp_k<<<ebt1, 256>>>(src1, 1, E1);
    ts_k<<<ebt1, 256>>>(src1, vscore, E1);
    topk_k<<<Q, 512>>>(maxep);
    scatter1_k<<<2000, 256>>>(src1, dst1, node_repr, vscore, out_score);

    // ---- layer 0 (no pruning); node_pre fuses repr update + resets ----
    node_pre3_k<<<nbn, 128>>>(node_repr, 1, N);
    edge_lin4_k<<<ebl0, 256>>>(src0, dst0, eg0, rel0, nullptr, 1, 0, E0);
    edge_exp_k<<<ebt0, 256>>>(src0, 0, E0);
    scatter0_k<<<ebl0, 256>>>(src0, dst0, E0);

    // ---- bypass_forward ----
    final3_k<<<nbn, 128>>>(Wlin, blin, out_repr, N);
}

// round 17
// speedup vs baseline: 1.0008x; 1.0003x over previous
#include <cuda_runtime.h>

// ---------------- problem-size capacities (fixed by dataset) ----------------
static const int NMAX  = 100000;
static const int EMAX  = 500000;
static const int QMAXC = 128;

// ---------------- device scratch (static; no allocation) --------------------
__device__ float    dM[128 * 128];          // M = Wq^T @ Wk
__device__ float    dGx[QMAXC * 32];
__device__ float    dGy[QMAXC * 32];
__device__ float    dGrel[QMAXC * 32];
__device__ float    dCq[QMAXC];
__device__ float    dZ[NMAX * 32];
__device__ float    dP[NMAX * 32];
__device__ float    dT[NMAX * 32];
__device__ float    dRepr[NMAX * 32];
__device__ float    dAgg[NMAX * 32];
__device__ float    dLogits1[EMAX];         // layer-1: quad term, then logit
__device__ float    dLogits0[EMAX];         // layer-0: quad term, then logit
__device__ float    dEx[EMAX];              // exp, then normalized w
__device__ unsigned dTsEnc[EMAX];
__device__ unsigned dNodeMax[NMAX];
__device__ float    dNodeSum[NMAX];
__device__ int      dOff[QMAXC + 1];
__device__ int      dKlist[EMAX];
__device__ int      dKcount;

// ---------------- helpers ----------------------------------------------------
__device__ __forceinline__ unsigned encf(float f) {
    unsigned u = __float_as_uint(f);
    return (u & 0x80000000u) ? ~u : (u | 0x80000000u);
}
__device__ __forceinline__ float decf(unsigned e) {
    unsigned u = (e & 0x80000000u) ? (e & 0x7FFFFFFFu) : ~e;
    return __uint_as_float(u);
}
__device__ __forceinline__ unsigned long long packf2(float lo, float hi) {
    unsigned long long r;
    asm("mov.b64 %0, {%1, %2};" : "=l"(r) : "f"(lo), "f"(hi));
    return r;
}
__device__ __forceinline__ void unpackf2(unsigned long long v, float& lo, float& hi) {
    asm("mov.b64 {%0, %1}, %2;" : "=f"(lo), "=f"(hi) : "l"(v));
}
__device__ __forceinline__ unsigned long long fmaf2(unsigned long long a, unsigned long long b,
                                                    unsigned long long c) {
    unsigned long long d;
    asm("fma.rn.f32x2 %0, %1, %2, %3;" : "=l"(d) : "l"(a), "l"(b), "l"(c));
    return d;
}
__device__ __forceinline__ void red4(float* p, float a, float b, float c, float d) {
    asm volatile("red.global.v4.f32.add [%0], {%1, %2, %3, %4};"
                 :: "l"(p), "f"(a), "f"(b), "f"(c), "f"(d) : "memory");
}
// streaming (evict-first) vector load: for single-use data
__device__ __forceinline__ float4 ldcs4(const float* p) {
    float4 v;
    asm volatile("ld.global.cs.v4.f32 {%0, %1, %2, %3}, [%4];"
                 : "=f"(v.x), "=f"(v.y), "=f"(v.z), "=f"(v.w) : "l"(p));
    return v;
}

// ---------------- prep: computeM + query_pre + group_off + resets -------------
__global__ void __launch_bounds__(128) prep_k(const float* __restrict__ Wq,
                                              const float* __restrict__ Wk,
                                              const float* __restrict__ qemb,
                                              const float* __restrict__ remb,
                                              const int* __restrict__ eg1,
                                              float* __restrict__ score_out,
                                              int N, int E1, int Q) {
    int b = blockIdx.x, t = threadIdx.x;
    if (b < 128) {
        int i = b, j = t;
        float acc = 0.f;
        #pragma unroll 8
        for (int o = 0; o < 128; o++)
            acc = fmaf(__ldg(&Wq[o * 128 + i]), __ldg(&Wk[o * 128 + j]), acc);
        dM[i * 128 + j] = acc;
        return;
    }
    if (b < 128 + Q) {
        if (t >= 32) return;
        int q = b - 128, d = t;
        __shared__ float qv[32], rv[32];
        qv[d] = qemb[q * 32 + d];
        rv[d] = remb[q * 32 + d];
        __syncwarp();
        __shared__ float su[128], sv[128];
        for (int o = d; o < 128; o += 32) {
            float uu = 0.f, vv = 0.f;
            #pragma unroll
            for (int c = 0; c < 32; c++) {
                uu = fmaf(__ldg(&Wk[o * 128 + 64 + c]), qv[c], uu);
                uu = fmaf(__ldg(&Wk[o * 128 + 96 + c]), rv[c], uu);
                vv = fmaf(__ldg(&Wq[o * 128 + 64 + c]), qv[c], vv);
                vv = fmaf(__ldg(&Wq[o * 128 + 96 + c]), rv[c], vv);
            }
            su[o] = uu; sv[o] = vv;
        }
        __syncwarp();
        float gx = 0.f, gy = 0.f, gr = 0.f, cq = 0.f;
        for (int o = 0; o < 128; o++) {
            float uo = su[o], vo = sv[o];
            gx = fmaf(__ldg(&Wq[o * 128 + d]), uo, gx);
            gy = fmaf(__ldg(&Wk[o * 128 + d]), vo, gy);
            gr = fmaf(__ldg(&Wq[o * 128 + 32 + d]), uo, gr);
            gr = fmaf(__ldg(&Wk[o * 128 + 32 + d]), vo, gr);
            if (d == 0) cq = fmaf(uo, vo, cq);
        }
        dGx[q * 32 + d] = gx;
        dGy[q * 32 + d] = gy;
        dGrel[q * 32 + d] = gr;
        if (d == 0) dCq[q] = cq;
        return;
    }
    if (b == 128 + Q) {
        for (int g = t; g <= Q; g += 128) {
            int lo = 0, hi = E1;
            while (lo < hi) {
                int mid = (lo + hi) >> 1;
                if (eg1[mid] < g) lo = mid + 1; else hi = mid;
            }
            dOff[g] = lo;
        }
        return;
    }
    // resets: float4-vectorized dAgg zeroing; per-node scalars alongside
    int i = (b - (129 + Q)) * 128 + t;             // float4 index over dAgg
    if (i < N * 8)
        reinterpret_cast<float4*>(dAgg)[i] = make_float4(0.f, 0.f, 0.f, 0.f);
    if (i < N) {
        dNodeMax[i] = 0u;
        dNodeSum[i] = 0.f;
        score_out[i] = 0.f;
    }
    if (i == 0) dKcount = 0;
}

// ---------------- device bodies: node precompute / quad -----------------------
// node body: 128 threads, 128 nodes. sW: 96*32 floats, sR: 128*33 floats.
__device__ __forceinline__ void node_pre_body(const float* __restrict__ repr_ext,
                                              int mode, int N, int base, int t,
                                              float* sW, float* sR) {
    for (int i = t; i < 96 * 32; i += 128) {
        int o = i >> 5, k = i & 31;
        float v;
        if (o < 32)      v = dM[o * 128 + k];
        else if (o < 64) v = dM[k * 128 + 32 + (o - 32)];
        else             v = dM[(32 + (o - 64)) * 128 + k];
        sW[i] = v;
    }
    if (mode == 0) {
        for (int i = t; i < 128 * 32; i += 128) {
            int n = base + (i >> 5);
            sR[(i >> 5) * 33 + (i & 31)] = (n < N) ? repr_ext[n * 32 + (i & 31)] : 0.f;
        }
    } else {
        for (int i = t; i < 128 * 32; i += 128) {
            int n = base + (i >> 5);
            float v = 0.f;
            if (n < N) {
                int g = n * 32 + (i & 31);
                v = fmaf(0.8f, dAgg[g], 0.2f * repr_ext[g]);
                dRepr[g] = v;
                dAgg[g] = 0.f;
            }
            sR[(i >> 5) * 33 + (i & 31)] = v;
        }
        int n = base + t;
        if (n < N) { dNodeMax[n] = 0u; dNodeSum[n] = 0.f; }
    }
    __syncthreads();
    float re[32];
    #pragma unroll
    for (int k = 0; k < 32; k++) re[k] = sR[t * 33 + k];

    const float4* Wv = reinterpret_cast<const float4*>(sW);
    bool live = (base + t) < N;
    #pragma unroll 1
    for (int c = 0; c < 3; c++) {
        float* out = (c == 0) ? dZ : (c == 1) ? dP : dT;
        #pragma unroll 1
        for (int h = 0; h < 2; h++) {
            float acc[16];
            #pragma unroll
            for (int o = 0; o < 16; o++) {
                int row = c * 32 + h * 16 + o;
                float a = 0.f;
                #pragma unroll
                for (int k4 = 0; k4 < 8; k4++) {
                    float4 m = Wv[row * 8 + k4];
                    a = fmaf(m.x, re[4 * k4 + 0], a);
                    a = fmaf(m.y, re[4 * k4 + 1], a);
                    a = fmaf(m.z, re[4 * k4 + 2], a);
                    a = fmaf(m.w, re[4 * k4 + 3], a);
                }
                acc[o] = a;
            }
            __syncthreads();
            if (live) {
                #pragma unroll
                for (int o = 0; o < 16; o++) sR[t * 17 + o] = acc[o];
            }
            __syncthreads();
            for (int i = t; i < 128 * 16; i += 128) {
                int n = base + (i >> 4);
                if (n < N) out[n * 32 + h * 16 + (i & 15)] = sR[(i >> 4) * 17 + (i & 15)];
            }
        }
    }
}

// quad body: 128 threads, 256 edges (2/thread via f32x2). sTri: 528 u64,
// sRe: 128*33 floats. rel read with streaming hint (single-use).
__device__ __forceinline__ void quad_body(const float* __restrict__ rel,
                                          float* __restrict__ out, int E,
                                          int base, int t,
                                          unsigned long long* sTri, float* sRe) {
    for (int i = t; i < 528; i += 128) {
        int j = 0, off = 0;
        while (off + (32 - j) <= i) { off += 32 - j; j++; }
        int k = j + (i - off);
        float v = (k == j) ? dM[(32 + j) * 128 + 32 + j]
                           : dM[(32 + j) * 128 + 32 + k] + dM[(32 + k) * 128 + 32 + j];
        sTri[i] = packf2(v, v);
    }
    // stage A: 128 edges (streaming loads)
    for (int i = t; i < 128 * 8; i += 128) {
        int erow = i >> 3, c4 = i & 7;
        int e = base + erow;
        float4 v = (e < E) ? ldcs4(&rel[(size_t)e * 32 + c4 * 4])
                           : make_float4(0.f, 0.f, 0.f, 0.f);
        sRe[erow * 33 + c4 * 4 + 0] = v.x;
        sRe[erow * 33 + c4 * 4 + 1] = v.y;
        sRe[erow * 33 + c4 * 4 + 2] = v.z;
        sRe[erow * 33 + c4 * 4 + 3] = v.w;
    }
    __syncthreads();
    float reA[32];
    #pragma unroll
    for (int k = 0; k < 32; k++) reA[k] = sRe[t * 33 + k];
    __syncthreads();
    for (int i = t; i < 128 * 8; i += 128) {
        int erow = i >> 3, c4 = i & 7;
        int e = base + 128 + erow;
        float4 v = (e < E) ? ldcs4(&rel[(size_t)e * 32 + c4 * 4])
                           : make_float4(0.f, 0.f, 0.f, 0.f);
        sRe[erow * 33 + c4 * 4 + 0] = v.x;
        sRe[erow * 33 + c4 * 4 + 1] = v.y;
        sRe[erow * 33 + c4 * 4 + 2] = v.z;
        sRe[erow * 33 + c4 * 4 + 3] = v.w;
    }
    __syncthreads();
    unsigned long long re2[32];
    #pragma unroll
    for (int k = 0; k < 32; k++) re2[k] = packf2(reA[k], sRe[t * 33 + k]);

    const unsigned long long z2 = packf2(0.f, 0.f);
    unsigned long long w2 = z2;
    #pragma unroll
    for (int j = 0; j < 32; j++) {
        const int off = 32 * j - (j * (j - 1)) / 2;
        unsigned long long v2 = fmaf2(sTri[off], re2[j], z2);
        #pragma unroll
        for (int k = j + 1; k < 32; k++)
            v2 = fmaf2(sTri[off + (k - j)], re2[k], v2);
        w2 = fmaf2(re2[j], v2, w2);
    }
    float wA, wB;
    unpackf2(w2, wA, wB);
    int eA = base + t, eB = base + 128 + t;
    if (eA < E) out[eA] = wA;
    if (eB < E) out[eB] = wB;
}

// ---------------- phase A: node_pre(mode 0) + quad(layer1) + quad(layer0) -----
static const int PHASEA_SMEM = 96 * 32 * 4 + 128 * 33 * 4;   // 29184 bytes
__global__ void __launch_bounds__(128) phaseA_k(const float* __restrict__ repr_ext,
                                                const float* __restrict__ rel1,
                                                const float* __restrict__ rel0,
                                                int N, int E1, int E0,
                                                int nbn, int nq1) {
    __shared__ __align__(16) char smemBuf[PHASEA_SMEM];
    int b = blockIdx.x, t = threadIdx.x;
    if (b < nbn) {
        float* sW = reinterpret_cast<float*>(smemBuf);
        float* sR = reinterpret_cast<float*>(smemBuf + 96 * 32 * 4);
        node_pre_body(repr_ext, 0, N, b * 128, t, sW, sR);
    } else {
        unsigned long long* sTri = reinterpret_cast<unsigned long long*>(smemBuf);
        float* sRe = reinterpret_cast<float*>(smemBuf + 4352);
        int qb = b - nbn;
        bool l1 = qb < nq1;
        quad_body(l1 ? rel1 : rel0, l1 ? dLogits1 : dLogits0,
                  l1 ? E1 : E0, (l1 ? qb : qb - nq1) * 256, t, sTri, sRe);
    }
}

// ---------------- node precompute standalone (layer 0, mode 1) ----------------
__global__ void __launch_bounds__(128, 6) node_pre3_k(const float* __restrict__ repr_ext,
                                                      int mode, int N) {
    __shared__ __align__(16) float sW[96 * 32];
    __shared__ float sR[128 * 33];
    node_pre_body(repr_ext, mode, N, blockIdx.x * 128, threadIdx.x, sW, sR);
}

// ---------------- linear logit terms: 4 edges per warp, 8 lanes each ----------
__global__ void __launch_bounds__(256) edge_lin4_k(const int* __restrict__ src,
                                                   const int* __restrict__ dst,
                                                   const int* __restrict__ eg,
                                                   const float* __restrict__ rel,
                                                   const float* repr_ext, int use_internal,
                                                   int layer1, int E) {
    const float* repr = use_internal ? dRepr : repr_ext;
    float* lgt = layer1 ? dLogits1 : dLogits0;
    unsigned gid = blockIdx.x * (unsigned)blockDim.x + threadIdx.x;
    int e = (int)(gid >> 3);          // 8 lanes per edge
    int q = (int)(gid & 7);
    bool valid = e < E;
    int ee = valid ? e : 0;
    int s = __ldg(&src[ee]), d = __ldg(&dst[ee]), g = __ldg(&eg[ee]);

    float4 x  = *reinterpret_cast<const float4*>(&repr[s * 32 + q * 4]);
    float4 y  = *reinterpret_cast<const float4*>(&repr[d * 32 + q * 4]);
    float4 zz = *reinterpret_cast<const float4*>(&dZ[d * 32 + q * 4]);
    float4 pp = *reinterpret_cast<const float4*>(&dP[s * 32 + q * 4]);
    float4 tt = *reinterpret_cast<const float4*>(&dT[d * 32 + q * 4]);
    float4 re = ldcs4(&rel[(size_t)ee * 32 + q * 4]);   // single-use stream
    float4 gx = *reinterpret_cast<const float4*>(&dGx[g * 32 + q * 4]);
    float4 gy = *reinterpret_cast<const float4*>(&dGy[g * 32 + q * 4]);
    float4 gr = *reinterpret_cast<const float4*>(&dGrel[g * 32 + q * 4]);

    float part = x.x * (zz.x + gx.x) + x.y * (zz.y + gx.y)
               + x.z * (zz.z + gx.z) + x.w * (zz.w + gx.w);
    part = fmaf(y.x, gy.x, part); part = fmaf(y.y, gy.y, part);
    part = fmaf(y.z, gy.z, part); part = fmaf(y.w, gy.w, part);
    part = fmaf(re.x, pp.x + tt.x + gr.x, part);
    part = fmaf(re.y, pp.y + tt.y + gr.y, part);
    part = fmaf(re.z, pp.z + tt.z + gr.z, part);
    part = fmaf(re.w, pp.w + tt.w + gr.w, part);

    part += __shfl_xor_sync(0xffffffffu, part, 1);
    part += __shfl_xor_sync(0xffffffffu, part, 2);
    part += __shfl_xor_sync(0xffffffffu, part, 4);

    if (valid && q == 0) {
        float logit = part + lgt[e] + dCq[g];
        lgt[e] = logit;
        atomicMax(&dNodeMax[s], encf(logit));
    }
}

// ---------------- exp(logit - max) + per-src sum -------------------------------
__global__ void edge_exp_k(const int* __restrict__ src, int layer1, int E) {
    int e = blockIdx.x * blockDim.x + threadIdx.x;
    if (e >= E) return;
    int s = src[e];
    float m = decf(dNodeMax[s]);
    float lg = layer1 ? dLogits1[e] : dLogits0[e];
    float ex = __expf(lg - m);
    dEx[e] = ex;
    atomicAdd(&dNodeSum[s], ex);
}

// ---------------- normalize + encoded target score (layer 1) ------------------
__global__ void ts_k(const int* __restrict__ src, const float* __restrict__ vscore, int E) {
    int e = blockIdx.x * blockDim.x + threadIdx.x;
    if (e >= E) return;
    int s = src[e];
    float w = __fdividef(dEx[e], dNodeSum[s]);
    dEx[e] = w;
    dTsEnc[e] = __float_as_uint(w * vscore[s]);
}

// ---------------- per-group top-k (stable: value desc, index asc), 512 thr ----
__global__ void __launch_bounds__(512) topk_k(const int* maxe) {
    int g = blockIdx.x;
    int lo = dOff[g], hi = dOff[g + 1];
    int len = hi - lo;
    if (len <= 0) return;
    int K = maxe ? maxe[0] : 500;
    if (K > len) K = len;

    __shared__ int hist[256];
    __shared__ int s_selbin, s_rem;
    unsigned prefix = 0u;
    int remaining = K;
    for (int shift = 24; shift >= 0; shift -= 8) {
        unsigned mask_hi = (shift == 24) ? 0u : (0xFFFFFFFFu << (shift + 8));
        for (int i = threadIdx.x; i < 256; i += blockDim.x) hist[i] = 0;
        __syncthreads();
        for (int i = lo + threadIdx.x; i < hi; i += blockDim.x) {
            unsigned v = dTsEnc[i];
            if ((v & mask_hi) == prefix) atomicAdd(&hist[(v >> shift) & 255], 1);
        }
        __syncthreads();
        if (threadIdx.x == 0) {
            int cum = 0, b = 255;
            for (; b > 0; b--) { cum += hist[b]; if (cum >= remaining) break; }
            if (cum < remaining) cum += hist[0];
            s_selbin = b;
            s_rem = remaining - (cum - hist[b]);
        }
        __syncthreads();
        prefix |= ((unsigned)s_selbin) << shift;
        remaining = s_rem;
        __syncthreads();
    }
    unsigned T = prefix;
    int quota_eq = remaining;

    __shared__ int warp_cnt[16];
    __shared__ int s_running;
    if (threadIdx.x == 0) s_running = 0;
    __syncthreads();
    for (int base = lo; base < hi; base += blockDim.x) {
        int i = base + (int)threadIdx.x;
        bool valid = i < hi;
        unsigned v = valid ? dTsEnc[i] : 0u;
        bool gt = valid && (v > T);
        bool eq = valid && (v == T);
        unsigned bal = __ballot_sync(0xffffffffu, eq);
        int lane = threadIdx.x & 31, wrp = threadIdx.x >> 5;
        int myrank = __popc(bal & ((1u << lane) - 1u));
        if (lane == 0) warp_cnt[wrp] = __popc(bal);
        __syncthreads();
        int woff = 0, chunk_tot = 0;
        #pragma unroll
        for (int ww = 0; ww < 16; ww++) {
            int c = warp_cnt[ww];
            if (ww < wrp) woff += c;
            chunk_tot += c;
        }
        int rank = s_running + woff + myrank;
        bool keep = gt || (eq && rank < quota_eq);
        if (keep) {
            int pos = atomicAdd(&dKcount, 1);
            dKlist[pos] = i;
        }
        __syncthreads();
        if (threadIdx.x == 0) s_running += chunk_tot;
        __syncthreads();
    }
}

// ---------------- layer-1 scatter (kept edges), 8 thr/edge, grid-stride -------
__global__ void scatter1_k(const int* __restrict__ src, const int* __restrict__ dst,
                           const float* __restrict__ node_repr, const float* __restrict__ vscore,
                           float* __restrict__ score_out) {
    unsigned gid = blockIdx.x * (unsigned)blockDim.x + threadIdx.x;
    int q = (int)(gid & 7);
    int stride = (int)((gridDim.x * (unsigned)blockDim.x) >> 3);
    int total = dKcount;
    for (int i = (int)(gid >> 3); i < total; i += stride) {
        int e = dKlist[i];
        int s = src[e], d = dst[e];
        float w = dEx[e];
        float4 v = *reinterpret_cast<const float4*>(&node_repr[s * 32 + q * 4]);
        red4(&dAgg[d * 32 + q * 4], w * v.x, w * v.y, w * v.z, w * v.w);
        if (q == 0) atomicAdd(&score_out[d], w * vscore[s]);
    }
}

// ---------------- layer-0 scatter (all edges); divide once per edge group -----
__global__ void scatter0_k(const int* __restrict__ src, const int* __restrict__ dst, int E) {
    unsigned gid = blockIdx.x * (unsigned)blockDim.x + threadIdx.x;
    int e = (int)(gid >> 3), q = (int)(gid & 7);
    if (e >= E) return;
    int s = src[e], d = dst[e];
    // lane 0 of each 8-lane group computes w; broadcast via shfl (same value,
    // bit-identical to per-lane divide). Groups never straddle warps.
    float w = 0.f;
    if (q == 0) w = __fdividef(dEx[e], dNodeSum[s]);
    int lane = threadIdx.x & 31;
    w = __shfl_sync(0xffffffffu, w, lane & ~7);
    float4 v = *reinterpret_cast<const float4*>(&dRepr[s * 32 + q * 4]);
    red4(&dAgg[d * 32 + q * 4], w * v.x, w * v.y, w * v.z, w * v.w);
}

// ---------------- final bypass: LeakyReLU(Wlin r2 + blin) ---------------------
__global__ void __launch_bounds__(128, 6) final3_k(const float* __restrict__ Wlin,
                                                   const float* __restrict__ blin,
                                                   float* __restrict__ out_repr, int N) {
    __shared__ __align__(16) float sW[1024];
    __shared__ float sR[128 * 33];
    __shared__ float sB[32];
    int t = threadIdx.x;
    for (int i = t; i < 1024; i += 128) sW[i] = Wlin[i];
    if (t < 32) sB[t] = blin[t];
    int base = blockIdx.x * 128;
    for (int i = t; i < 128 * 32; i += 128) {
        int n = base + (i >> 5);
        float v = 0.f;
        if (n < N) {
            int g = n * 32 + (i & 31);
            v = fmaf(0.8f, dAgg[g], 0.2f * dRepr[g]);
        }
        sR[(i >> 5) * 33 + (i & 31)] = v;
    }
    __syncthreads();
    float re[32];
    #pragma unroll
    for (int k = 0; k < 32; k++) re[k] = sR[t * 33 + k];
    const float4* Wv = reinterpret_cast<const float4*>(sW);
    bool live = (base + t) < N;
    #pragma unroll 1
    for (int h = 0; h < 2; h++) {
        float acc[16];
        #pragma unroll
        for (int o = 0; o < 16; o++) {
            int row = h * 16 + o;
            float a = sB[row];
            #pragma unroll
            for (int k4 = 0; k4 < 8; k4++) {
                float4 m = Wv[row * 8 + k4];
                a = fmaf(m.x, re[4 * k4 + 0], a);
                a = fmaf(m.y, re[4 * k4 + 1], a);
                a = fmaf(m.z, re[4 * k4 + 2], a);
                a = fmaf(m.w, re[4 * k4 + 3], a);
            }
            acc[o] = (a >= 0.f) ? a : 0.01f * a;
        }
        __syncthreads();
        if (live) {
            #pragma unroll
            for (int o = 0; o < 16; o++) sR[t * 17 + o] = acc[o];
        }
        __syncthreads();
        for (int i = t; i < 128 * 16; i += 128) {
            int n = base + (i >> 4);
            if (n < N) out_repr[n * 32 + h * 16 + (i & 15)] = sR[(i >> 4) * 17 + (i & 15)];
        }
    }
}

// ---------------- launcher ----------------------------------------------------
extern "C" void kernel_launch(void* const* d_in, const int* in_sizes, int n_in,
                              void* d_out, int out_size) {
    const float* vscore    = (const float*)d_in[0];
    const float* node_repr = (const float*)d_in[1];
    const int*   eg0       = (const int*)d_in[2];
    const int*   src0      = (const int*)d_in[3];
    const int*   dst0      = (const int*)d_in[4];
    const float* rel0      = (const float*)d_in[5];
    const int*   eg1       = (const int*)d_in[6];
    const int*   src1      = (const int*)d_in[7];
    const int*   dst1      = (const int*)d_in[8];
    const float* rel1      = (const float*)d_in[9];
    const float* qemb      = (const float*)d_in[10];
    const float* remb      = (const float*)d_in[11];
    const float* Wq        = (const float*)d_in[12];
    const float* Wk        = (const float*)d_in[13];
    const float* Wlin      = (const float*)d_in[14];
    const float* blin      = (const float*)d_in[15];
    const int*   maxep     = (n_in > 16) ? (const int*)d_in[16] : nullptr;

    int N  = in_sizes[0];
    int E0 = in_sizes[2];
    int E1 = in_sizes[6];
    int Q  = in_sizes[10] / 32;

    float* out_score = (float*)d_out;
    float* out_repr  = (float*)d_out + N;

    int nbn  = (N + 127) / 128;
    int nq0  = (E0 + 255) / 256;            // 256 edges per quad block
    int nq1  = (E1 + 255) / 256;
    int ebl0 = (E0 * 8 + 255) / 256;        // 8 lanes/edge
    int ebl1 = (E1 * 8 + 255) / 256;
    int ebt0 = (E0 + 255) / 256;
    int ebt1 = (E1 + 255) / 256;
    int nrst = (N * 8 + 127) / 128;         // float4 resets over dAgg

    // ---- prep: M, per-query vectors, group offsets, resets ----
    prep_k<<<129 + Q + nrst, 128>>>(Wq, Wk, qemb, remb, eg1, out_score, N, E1, Q);

    // ---- phase A (merged): node_pre(layer-1 input) + quad for BOTH layers ----
    phaseA_k<<<nbn + nq1 + nq0, 128>>>(node_repr, rel1, rel0, N, E1, E0, nbn, nq1);

    // ---- layer 1 (pruned) ----
    edge_lin4_k<<<ebl1, 256>>>(src1, dst1, eg1, rel1, node_repr, 0, 1, E1);
    edge_exp_k<<<ebt1, 256>>>(src1, 1, E1);
    ts_k<<<ebt1, 256>>>(src1, vscore, E1);
    topk_k<<<Q, 512>>>(maxep);
    scatter1_k<<<2000, 256>>>(src1, dst1, node_repr, vscore, out_score);

    // ---- layer 0 (no pruning); node_pre fuses repr update + resets ----
    node_pre3_k<<<nbn, 128>>>(node_repr, 1, N);
    edge_lin4_k<<<ebl0, 256>>>(src0, dst0, eg0, rel0, nullptr, 1, 0, E0);
    edge_exp_k<<<ebt0, 256>>>(src0, 0, E0);
    scatter0_k<<<ebl0, 256>>>(src0, dst0, E0);

    // ---- bypass_forward ----
    final3_k<<<nbn, 128>>>(Wlin, blin, out_repr, N);
}